// round 16
// baseline (speedup 1.0000x reference)
#include <cuda_runtime.h>
#include <cuda_fp16.h>
#include <cstdint>
#include <cstddef>

// ---------------------------------------------------------------------------
// GraphMoEDualRouter — GB300 sm_103a.
// Round 15: layer-0 GEMMs for all 8 experts merged into ONE launch
// (shared A operand [h16|agg0] read once, one solid wave at the fork).
// 8-stream chains + atomicAdd output from round 14 otherwise unchanged.
// ---------------------------------------------------------------------------

#define HDIM 256
#define NEXP 8
#define NGRAPH 64
#define MAXN 50176
#define MAXE 1600000

typedef unsigned long long ull;

// ---- scratch (static device memory; allocation is forbidden) ----
__device__ float  g_h    [MAXN * HDIM];                 // fp32 h (router)
__device__ __half g_h16  [MAXN * HDIM];                 // fp16 h (experts)
__device__ float  g_hs   [MAXN * HDIM];                 // router hidden
__device__ __half g_agg0 [MAXN * HDIM];
__device__ __half g_zA   [NEXP][MAXN * HDIM];
__device__ __half g_zB   [NEXP][MAXN * HDIM];
__device__ __half g_agT  [NEXP][MAXN * HDIM];
__device__ float  g_sparse[MAXN * NEXP];
__device__ int    g_xidx  [NEXP][MAXN];                 // per-expert gated nodes
__device__ int    g_xcnt  [NEXP];
__device__ int    g_deg   [MAXN];
__device__ int    g_rowptr[MAXN + 1];
__device__ int    g_cursor[MAXN];
__device__ int    g_colsrc[MAXE];
__device__ int    g_bsum  [64];
__device__ int    g_boff  [64];
__device__ int    g_ng[NGRAPH];
__device__ int    g_eg[NGRAPH];
__device__ float  g_strug[NGRAPH * NEXP];
// packed transposed fp16 weights: [24 mats][256 nrows][512 k]
__device__ __half g_wTh[24 * 256 * 512];

// ---- host-side streams/events (created once, pre-main; host resources only)
struct StreamPool {
    cudaStream_t s[10];       // 0-7 expert chains, 8 router, 9 encode
    cudaEvent_t evA, evB, evE, fork, ev0, join[NEXP];
    StreamPool() {
        for (int i = 0; i < 10; i++)
            cudaStreamCreateWithFlags(&s[i], cudaStreamNonBlocking);
        cudaEventCreateWithFlags(&evA,  cudaEventDisableTiming);
        cudaEventCreateWithFlags(&evB,  cudaEventDisableTiming);
        cudaEventCreateWithFlags(&evE,  cudaEventDisableTiming);
        cudaEventCreateWithFlags(&fork, cudaEventDisableTiming);
        cudaEventCreateWithFlags(&ev0,  cudaEventDisableTiming);
        for (int i = 0; i < NEXP; i++)
            cudaEventCreateWithFlags(&join[i], cudaEventDisableTiming);
    }
};
static StreamPool g_sp;

// ---- helpers ----
__device__ __forceinline__ ull pack2(float lo, float hi) {
    ull r; asm("mov.b64 %0, {%1, %2};" : "=l"(r) : "f"(lo), "f"(hi)); return r;
}
__device__ __forceinline__ void fma2acc(ull& d, ull a, ull b) {
    asm("fma.rn.f32x2 %0, %1, %2, %0;" : "+l"(d) : "l"(a), "l"(b));
}
__device__ __forceinline__ void unpack2(ull v, float& lo, float& hi) {
    asm("mov.b64 {%0, %1}, %2;" : "=f"(lo), "=f"(hi) : "l"(v));
}
__device__ __forceinline__ void mma_f16(float* d, const uint32_t* a, const uint32_t* b) {
    asm volatile(
        "mma.sync.aligned.m16n8k16.row.col.f32.f16.f16.f32 "
        "{%0,%1,%2,%3}, {%4,%5,%6,%7}, {%8,%9}, {%0,%1,%2,%3};"
        : "+f"(d[0]), "+f"(d[1]), "+f"(d[2]), "+f"(d[3])
        : "r"(a[0]), "r"(a[1]), "r"(a[2]), "r"(a[3]), "r"(b[0]), "r"(b[1]));
}
__device__ __forceinline__ void ldsm_x4(uint32_t& r0, uint32_t& r1,
                                        uint32_t& r2, uint32_t& r3, uint32_t addr) {
    asm volatile("ldmatrix.sync.aligned.m8n8.x4.shared.b16 {%0,%1,%2,%3}, [%4];"
        : "=r"(r0), "=r"(r1), "=r"(r2), "=r"(r3) : "r"(addr));
}
__device__ __forceinline__ uint32_t smem_u32(const void* p) {
    uint32_t a;
    asm("{ .reg .u64 t; cvta.to.shared.u64 t, %1; cvt.u32.u64 %0, t; }" : "=r"(a) : "l"(p));
    return a;
}
__device__ __forceinline__ void cp16(uint32_t dst, const void* src, int sz) {
    asm volatile("cp.async.cg.shared.global [%0], [%1], 16, %2;"
                 :: "r"(dst), "l"(src), "r"(sz) : "memory");
}
__device__ __forceinline__ void cp16u(uint32_t dst, const void* src) {
    asm volatile("cp.async.cg.shared.global [%0], [%1], 16;"
                 :: "r"(dst), "l"(src) : "memory");
}
__device__ __forceinline__ void acc8(float* a, uint4 v) {
    const __half2* p = (const __half2*)&v;
    #pragma unroll
    for (int q = 0; q < 4; q++) {
        float2 f = __half22float2(p[q]);
        a[2 * q]     += f.x;
        a[2 * q + 1] += f.y;
    }
}

// ===========================================================================
// Small kernels
// ===========================================================================
__global__ void k_hist_nodes(const int* __restrict__ batch, int* __restrict__ ng, int n) {
    __shared__ int sh[NGRAPH];
    if (threadIdx.x < NGRAPH) sh[threadIdx.x] = 0;
    __syncthreads();
    for (int i = blockIdx.x * blockDim.x + threadIdx.x; i < n; i += gridDim.x * blockDim.x)
        atomicAdd(&sh[batch[i]], 1);
    __syncthreads();
    if (threadIdx.x < NGRAPH) atomicAdd(&ng[threadIdx.x], sh[threadIdx.x]);
}

__global__ void k_hist_edges(const int* __restrict__ batch, const int* __restrict__ src,
                             int* __restrict__ eg, int e) {
    __shared__ int sh[NGRAPH];
    if (threadIdx.x < NGRAPH) sh[threadIdx.x] = 0;
    __syncthreads();
    for (int i = blockIdx.x * blockDim.x + threadIdx.x; i < e; i += gridDim.x * blockDim.x)
        atomicAdd(&sh[batch[src[i]]], 1);
    __syncthreads();
    if (threadIdx.x < NGRAPH) atomicAdd(&eg[threadIdx.x], sh[threadIdx.x]);
}

__global__ void k_stru(const int* __restrict__ ng, const int* __restrict__ eg,
                       const float* __restrict__ Wt1, const float* __restrict__ bt1,
                       const float* __restrict__ Wt2, const float* __restrict__ bt2,
                       float* __restrict__ strug) {
    int g = blockIdx.x;
    float fn = log1pf((float)ng[g]);
    float fe = log1pf((float)eg[g]);
    __shared__ float hid[HDIM];
    int j = threadIdx.x;
    hid[j] = fmaxf(fmaf(fn, Wt1[j], fmaf(fe, Wt1[HDIM + j], bt1[j])), 0.0f);
    __syncthreads();
    int w = threadIdx.x >> 5, lane = threadIdx.x & 31;
    if (w < NEXP) {
        float acc = 0.f;
        for (int k = lane; k < HDIM; k += 32) acc = fmaf(hid[k], Wt2[k * NEXP + w], acc);
        #pragma unroll
        for (int off = 16; off; off >>= 1) acc += __shfl_down_sync(0xffffffffu, acc, off);
        if (lane == 0) strug[g * NEXP + w] = acc + bt2[w];
    }
}

__global__ void k_encode(const float* __restrict__ x, const float* __restrict__ W,
                         const float* __restrict__ b, float* __restrict__ h,
                         __half* __restrict__ h16, int n) {
    int node = blockIdx.x;
    if (node >= n) return;
    __shared__ float xs[6];
    if (threadIdx.x < 6) xs[threadIdx.x] = x[node * 10 + 4 + threadIdx.x];
    __syncthreads();
    int j = threadIdx.x;
    float acc = b[j];
    #pragma unroll
    for (int k = 0; k < 6; k++) acc = fmaf(xs[k], W[k * HDIM + j], acc);
    float v = fmaxf(acc, 0.0f);
    h[(size_t)node * HDIM + j] = v;
    h16[(size_t)node * HDIM + j] = __float2half_rn(v);
}

// ===========================================================================
// FFMA fp32 GEMM — router hidden layer only (top-2 selection needs exactness)
// ===========================================================================
#define BMR 128
#define BNR 64
#define BKR 16

__global__ __launch_bounds__(256) void k_gemm(
    const float* __restrict__ A, const float* __restrict__ W1,
    const float* __restrict__ bias, int n, float* __restrict__ C)
{
    __shared__ __align__(16) float As[BKR][BMR + 2];
    __shared__ __align__(16) float Ws[BKR][BNR];

    int m0 = blockIdx.x * BMR;
    int n0 = blockIdx.y * BNR;
    int tid = threadIdx.x;
    int tm = tid >> 4;
    int tn = tid & 15;

    ull acc2[4][4];
    #pragma unroll
    for (int i = 0; i < 4; i++)
        #pragma unroll
        for (int j = 0; j < 4; j++) acc2[i][j] = 0ull;

    for (int kc = 0; kc < HDIM; kc += BKR) {
        #pragma unroll
        for (int u = 0; u < 2; u++) {
            int idx = tid + u * 256;
            int row = idx >> 2;
            int kq  = idx & 3;
            float4 v = make_float4(0.f, 0.f, 0.f, 0.f);
            int gr = m0 + row;
            if (gr < n) v = *(const float4*)(A + (size_t)gr * HDIM + kc + kq * 4);
            As[kq * 4 + 0][row] = v.x;
            As[kq * 4 + 1][row] = v.y;
            As[kq * 4 + 2][row] = v.z;
            As[kq * 4 + 3][row] = v.w;
        }
        {
            int kk = tid >> 4, nq = tid & 15;
            float4 w = *(const float4*)(W1 + (size_t)(kc + kk) * HDIM + n0 + nq * 4);
            *(float4*)&Ws[kk][nq * 4] = w;
        }
        __syncthreads();
        #pragma unroll
        for (int kk = 0; kk < BKR; kk++) {
            ull a2[4];
            #pragma unroll
            for (int i2 = 0; i2 < 4; i2++)
                a2[i2] = *(const ull*)&As[kk][tm * 8 + i2 * 2];
            #pragma unroll
            for (int j = 0; j < 4; j++) {
                float bb = Ws[kk][tn * 4 + j];
                ull b2 = pack2(bb, bb);
                #pragma unroll
                for (int i2 = 0; i2 < 4; i2++) fma2acc(acc2[i2][j], a2[i2], b2);
            }
        }
        __syncthreads();
    }

    float4 bb4 = *(const float4*)&bias[n0 + tn * 4];
    #pragma unroll
    for (int i2 = 0; i2 < 4; i2++) {
        float4 vlo, vhi;
        unpack2(acc2[i2][0], vlo.x, vhi.x);
        unpack2(acc2[i2][1], vlo.y, vhi.y);
        unpack2(acc2[i2][2], vlo.z, vhi.z);
        unpack2(acc2[i2][3], vlo.w, vhi.w);
        #pragma unroll
        for (int rr = 0; rr < 2; rr++) {
            int row = m0 + tm * 8 + i2 * 2 + rr;
            if (row >= n) continue;
            float4 v = rr ? vhi : vlo;
            v.x = fmaxf(v.x + bb4.x, 0.f); v.y = fmaxf(v.y + bb4.y, 0.f);
            v.z = fmaxf(v.z + bb4.z, 0.f); v.w = fmaxf(v.w + bb4.w, 0.f);
            *(float4*)(C + (size_t)row * HDIM + n0 + tn * 4) = v;
        }
    }
}

// ===========================================================================
// Router logits + top-2 sparse gates + per-expert compacted node lists
// ===========================================================================
__global__ void k_logits(const float* __restrict__ hs, const float* __restrict__ Ws2,
                         const float* __restrict__ bs2, const float* __restrict__ strug,
                         const int* __restrict__ batch, float* __restrict__ sparse,
                         int* __restrict__ xidx, int* __restrict__ xcnt, int n) {
    int warp = (blockIdx.x * blockDim.x + threadIdx.x) >> 5;
    int lane = threadIdx.x & 31;
    if (warp >= n) return;
    const float* row = hs + (size_t)warp * HDIM;
    float acc[NEXP];
    #pragma unroll
    for (int o = 0; o < NEXP; o++) acc[o] = 0.f;
    for (int k = lane; k < HDIM; k += 32) {
        float v = row[k];
        const float* w2 = Ws2 + k * NEXP;
        #pragma unroll
        for (int o = 0; o < NEXP; o++) acc[o] = fmaf(v, w2[o], acc[o]);
    }
    #pragma unroll
    for (int o = 0; o < NEXP; o++)
        #pragma unroll
        for (int off = 16; off; off >>= 1) acc[o] += __shfl_down_sync(0xffffffffu, acc[o], off);
    if (lane == 0) {
        int g = batch[warp];
        float lg[NEXP];
        #pragma unroll
        for (int o = 0; o < NEXP; o++)
            lg[o] = 0.5f * (acc[o] + bs2[o]) + 0.5f * strug[g * NEXP + o];
        float m1 = -3.4e38f; int i1 = 0;
        #pragma unroll
        for (int o = 0; o < NEXP; o++) if (lg[o] > m1) { m1 = lg[o]; i1 = o; }
        float m2 = -3.4e38f; int i2 = 0;
        #pragma unroll
        for (int o = 0; o < NEXP; o++) if (o != i1 && lg[o] > m2) { m2 = lg[o]; i2 = o; }
        float e2 = __expf(m2 - m1);
        float inv = 1.0f / (1.0f + e2);
        float* srow = sparse + (size_t)warp * NEXP;
        #pragma unroll
        for (int o = 0; o < NEXP; o++) srow[o] = 0.f;
        srow[i1] = inv;
        srow[i2] = e2 * inv;
        int p1 = atomicAdd(&xcnt[i1], 1);
        xidx[i1 * MAXN + p1] = warp;
        int p2 = atomicAdd(&xcnt[i2], 1);
        xidx[i2 * MAXN + p2] = warp;
    }
}

// ===========================================================================
// CSR build: counting sort by dst with 3-phase multi-block scan
// ===========================================================================
__global__ void k_deg(const int* __restrict__ dst, int* __restrict__ deg, int e) {
    int i = blockIdx.x * blockDim.x + threadIdx.x;
    if (i < e) atomicAdd(&deg[dst[i]], 1);
}

__global__ void k_scan1(const int* __restrict__ deg, int* __restrict__ rowptr,
                        int* __restrict__ bsum, int n) {
    __shared__ int sh[1024];
    int i = blockIdx.x * 1024 + threadIdx.x;
    int v = (i < n) ? deg[i] : 0;
    sh[threadIdx.x] = v;
    __syncthreads();
    #pragma unroll
    for (int off = 1; off < 1024; off <<= 1) {
        int t = (threadIdx.x >= (unsigned)off) ? sh[threadIdx.x - off] : 0;
        __syncthreads();
        sh[threadIdx.x] += t;
        __syncthreads();
    }
    if (i < n) rowptr[i + 1] = sh[threadIdx.x];
    if (threadIdx.x == 1023) bsum[blockIdx.x] = sh[1023];
}

__global__ void k_scan2(const int* __restrict__ bsum, int* __restrict__ boff, int nb) {
    __shared__ int sh[64];
    int i = threadIdx.x;
    int orig = (i < nb) ? bsum[i] : 0;
    sh[i] = orig;
    __syncthreads();
    #pragma unroll
    for (int off = 1; off < 64; off <<= 1) {
        int t = (i >= off) ? sh[i - off] : 0;
        __syncthreads();
        sh[i] += t;
        __syncthreads();
    }
    if (i < nb) boff[i] = sh[i] - orig;
}

__global__ void k_scan3(const int* __restrict__ deg, int* __restrict__ rowptr,
                        const int* __restrict__ boff, int* __restrict__ cursor, int n) {
    int i = blockIdx.x * 1024 + threadIdx.x;
    if (i == 0) rowptr[0] = 0;
    if (i < n) {
        int inc = rowptr[i + 1] + boff[blockIdx.x];
        rowptr[i + 1] = inc;
        cursor[i] = inc - deg[i];
    }
}

__global__ void k_sortedges(const int* __restrict__ src, const int* __restrict__ dst,
                            int* __restrict__ cursor, int* __restrict__ colsrc, int e) {
    int i = blockIdx.x * blockDim.x + threadIdx.x;
    if (i < e) {
        int d = dst[i];
        int p = atomicAdd(&cursor[d], 1);
        colsrc[p] = src[i];
    }
}

// ===========================================================================
// fp16 CSR gather aggregation (fp32 accum) — warp per node, LDG.128 lanes.
// ===========================================================================
__global__ __launch_bounds__(256) void k_agg(const uint4* __restrict__ z,
                                             uint4* __restrict__ agg,
                                             const int* __restrict__ rowptr,
                                             const int* __restrict__ colsrc, int n,
                                             const int* __restrict__ ridx,
                                             const int* __restrict__ cntp) {
    int w = blockIdx.x * 8 + (threadIdx.x >> 5);
    int lane = threadIdx.x & 31;
    int cnt = (ridx != nullptr) ? *cntp : n;
    if (w >= cnt) return;
    int node = (ridx != nullptr) ? ridx[w] : w;
    int s0 = rowptr[node], s1 = rowptr[node + 1];

    float a0[8], a1[8], a2[8], a3[8];
    #pragma unroll
    for (int k = 0; k < 8; k++) { a0[k] = a1[k] = a2[k] = a3[k] = 0.f; }

    int i = s0;
    for (; i + 3 < s1; i += 4) {
        int sA = colsrc[i], sB = colsrc[i + 1], sC = colsrc[i + 2], sD = colsrc[i + 3];
        uint4 vA = z[(size_t)sA * 32 + lane];
        uint4 vB = z[(size_t)sB * 32 + lane];
        uint4 vC = z[(size_t)sC * 32 + lane];
        uint4 vD = z[(size_t)sD * 32 + lane];
        acc8(a0, vA); acc8(a1, vB); acc8(a2, vC); acc8(a3, vD);
    }
    for (; i < s1; i++) acc8(a0, z[(size_t)colsrc[i] * 32 + lane]);

    uint4 o;
    __half2* op = (__half2*)&o;
    #pragma unroll
    for (int q = 0; q < 4; q++) {
        float rx = (a0[2 * q]     + a1[2 * q])     + (a2[2 * q]     + a3[2 * q]);
        float ry = (a0[2 * q + 1] + a1[2 * q + 1]) + (a2[2 * q + 1] + a3[2 * q + 1]);
        op[q] = __floats2half2_rn(rx, ry);
    }
    agg[(size_t)node * 32 + lane] = o;
}

// ===========================================================================
// Weight pack
// ===========================================================================
__global__ void k_pack(const float* __restrict__ Wself, const float* __restrict__ Wnei,
                       __half* __restrict__ wTh) {
    int idx = blockIdx.x * 256 + threadIdx.x;
    int k = idx & 511;
    int rem = idx >> 9;
    int nrow = rem & 255;
    int mat = rem >> 8;
    const float* srcp = (k < 256) ? Wself : Wnei;
    int kk = k & 255;
    wTh[idx] = __float2half_rn(srcp[((size_t)mat * 256 + kk) * 256 + nrow]);
}

// ===========================================================================
// fp16 mma.sync dual GEMM; ldmatrix fragment loads; optional row list.
// Expert-batched mode (ebatch != 0): blockIdx.y in [0, 2*NEXP);
//   expert eb = y>>1, n0 = (y&1)*128; WTh/bias/Ch offset by per-expert strides.
// Final mode (Cf != null): out[node] += gate * val via fp32 atomicAdd.
// ===========================================================================
#define PADH 72
#define HBUF (128 * PADH)
#define TM_SMEM (4 * HBUF * 2)

__global__ __launch_bounds__(256, 2) void k_tmma(
    const __half* __restrict__ Az, const __half* __restrict__ Ag,
    const __half* __restrict__ WTh, const float* __restrict__ bias,
    int n, int relu, __half* __restrict__ Ch, float* __restrict__ Cf,
    const float* __restrict__ sparse, int expert,
    const int* __restrict__ ridx, const int* __restrict__ cntp,
    int ebatch, int wstep, long cstep, int bstep)
{
    extern __shared__ __half smh[];
    __shared__ int rid_s[128];
    uint32_t sbase = smem_u32(smh);

    int tid = threadIdx.x;
    int warp = tid >> 5, lane = tid & 31;
    int m0 = blockIdx.x * 128;
    int n0;
    if (ebatch) {
        int eb = blockIdx.y >> 1;
        n0 = (blockIdx.y & 1) * 128;
        WTh  += (size_t)eb * wstep;
        bias += (size_t)eb * bstep;
        Ch   += (size_t)eb * cstep;
    } else {
        n0 = blockIdx.y * 128;
    }
    int m_off = (warp >> 1) * 32;
    int n_off = (warp & 1) * 64;
    int g = lane >> 2, t = lane & 3;

    int mrows = (cntp != nullptr) ? *cntp : n;
    if (m0 >= mrows) return;

    if (tid < 128) {
        int gr = m0 + tid;
        rid_s[tid] = (gr < mrows) ? ((ridx != nullptr) ? ridx[gr] : gr) : 0;
    }
    __syncthreads();

    float acc[2][8][4];
    #pragma unroll
    for (int i = 0; i < 2; i++)
        #pragma unroll
        for (int j = 0; j < 8; j++)
            #pragma unroll
            for (int r = 0; r < 4; r++) acc[i][j][r] = 0.f;

    auto issue_chunk = [&](int c, int buf) {
        const __half* Asrc = (c < 4) ? Az : Ag;
        int kb = (c & 3) * 64;
        uint32_t abase = sbase + (uint32_t)buf * (HBUF * 2);
        uint32_t bbase = sbase + (uint32_t)(2 + buf) * (HBUF * 2);
        #pragma unroll
        for (int i = 0; i < 4; i++) {
            int idx = tid + i * 256;
            int row = idx >> 3, q = idx & 7;
            int gr = m0 + row;
            int node = rid_s[row];
            cp16(abase + (uint32_t)(row * (PADH * 2) + q * 16),
                 Asrc + (size_t)node * HDIM + kb + q * 8,
                 (gr < mrows) ? 16 : 0);
            cp16u(bbase + (uint32_t)(row * (PADH * 2) + q * 16),
                  WTh + (size_t)(n0 + row) * 512 + c * 64 + q * 8);
        }
        asm volatile("cp.async.commit_group;" ::: "memory");
    };

    int a_row = m_off + (lane & 7) + ((lane >> 3) & 1) * 8;
    int a_kh  = (lane >> 4) * 8;
    uint32_t a_off0 = (uint32_t)(a_row * PADH + a_kh) * 2;
    int b_row = n_off + ((lane >> 4) & 1) * 8 + (lane & 7);
    int b_kh  = ((lane >> 3) & 1) * 8;
    uint32_t b_off0 = (uint32_t)(b_row * PADH + b_kh) * 2;

    issue_chunk(0, 0);

    for (int c = 0; c < 8; c++) {
        int buf = c & 1;
        if (c < 7) {
            issue_chunk(c + 1, buf ^ 1);
            asm volatile("cp.async.wait_group 1;" ::: "memory");
        } else {
            asm volatile("cp.async.wait_group 0;" ::: "memory");
        }
        __syncthreads();

        uint32_t a_sm = sbase + (uint32_t)buf * (HBUF * 2) + a_off0;
        uint32_t b_sm = sbase + (uint32_t)(2 + buf) * (HBUF * 2) + b_off0;
        #pragma unroll
        for (int ks = 0; ks < 4; ks++) {
            uint32_t koff = (uint32_t)(ks * 16) * 2;
            uint32_t af[2][4], bf[8][2];
            ldsm_x4(af[0][0], af[0][1], af[0][2], af[0][3], a_sm + koff);
            ldsm_x4(af[1][0], af[1][1], af[1][2], af[1][3],
                    a_sm + (uint32_t)(16 * PADH) * 2 + koff);
            #pragma unroll
            for (int q = 0; q < 4; q++)
                ldsm_x4(bf[2 * q][0], bf[2 * q][1], bf[2 * q + 1][0], bf[2 * q + 1][1],
                        b_sm + (uint32_t)(q * 16 * PADH) * 2 + koff);
            #pragma unroll
            for (int i = 0; i < 2; i++)
                #pragma unroll
                for (int j = 0; j < 8; j++)
                    mma_f16(acc[i][j], af[i], bf[j]);
        }
        __syncthreads();
    }

    // ---- epilogue ----
    #pragma unroll
    for (int i = 0; i < 2; i++) {
        int l0 = m_off + i * 16 + g;
        int l1 = l0 + 8;
        bool v0r = (m0 + l0) < mrows;
        bool v1r = (m0 + l1) < mrows;
        int node0 = rid_s[l0];
        int node1 = rid_s[l1];
        float s0 = 0.f, s1 = 0.f;
        if (Cf != nullptr) {
            if (v0r) s0 = sparse[(size_t)node0 * NEXP + expert];
            if (v1r) s1 = sparse[(size_t)node1 * NEXP + expert];
        }
        #pragma unroll
        for (int j = 0; j < 8; j++) {
            int col = n0 + n_off + j * 8 + 2 * t;
            float2 bb2 = *(const float2*)(bias + col);
            float2 v0, v1;
            v0.x = acc[i][j][0] + bb2.x; v0.y = acc[i][j][1] + bb2.y;
            v1.x = acc[i][j][2] + bb2.x; v1.y = acc[i][j][3] + bb2.y;
            if (relu) {
                v0.x = fmaxf(v0.x, 0.f); v0.y = fmaxf(v0.y, 0.f);
                v1.x = fmaxf(v1.x, 0.f); v1.y = fmaxf(v1.y, 0.f);
            }
            if (Cf != nullptr) {
                if (v0r) {
                    float* op = Cf + (size_t)node0 * HDIM + col;
                    atomicAdd(op,     s0 * v0.x);
                    atomicAdd(op + 1, s0 * v0.y);
                }
                if (v1r) {
                    float* op = Cf + (size_t)node1 * HDIM + col;
                    atomicAdd(op,     s1 * v1.x);
                    atomicAdd(op + 1, s1 * v1.y);
                }
            } else {
                if (v0r) *(__half2*)(Ch + (size_t)node0 * HDIM + col) = __floats2half2_rn(v0.x, v0.y);
                if (v1r) *(__half2*)(Ch + (size_t)node1 * HDIM + col) = __floats2half2_rn(v1.x, v1.y);
            }
        }
    }
}

// ===========================================================================
// host launch
// ===========================================================================
extern "C" void kernel_launch(void* const* d_in, const int* in_sizes, int n_in,
                              void* d_out, int out_size) {
    const float* x      = (const float*)d_in[0];
    const int*   ei     = (const int*)  d_in[1];
    const int*   batch  = (const int*)  d_in[2];
    const float* W_enc  = (const float*)d_in[3];
    const float* b_enc  = (const float*)d_in[4];
    const float* Ws1    = (const float*)d_in[5];
    const float* bs1    = (const float*)d_in[6];
    const float* Ws2    = (const float*)d_in[7];
    const float* bs2    = (const float*)d_in[8];
    const float* Wt1    = (const float*)d_in[9];
    const float* bt1    = (const float*)d_in[10];
    const float* Wt2    = (const float*)d_in[11];
    const float* bt2    = (const float*)d_in[12];
    const float* W_self = (const float*)d_in[13];
    const float* W_nei  = (const float*)d_in[14];
    const float* b_exp  = (const float*)d_in[15];

    int N = in_sizes[0] / 10;
    int E = in_sizes[1] / 2;
    const int* src = ei;
    const int* dst = ei + E;
    float* out = (float*)d_out;

    float *h, *hs, *sparse, *strug;
    __half *h16, *agg0, *zA, *zB, *agT, *wTh;
    int *deg, *rowptr, *cursor, *colsrc, *ng, *eg, *bsum, *boff, *xidx, *xcnt;
    cudaGetSymbolAddress((void**)&h,      g_h);
    cudaGetSymbolAddress((void**)&h16,    g_h16);
    cudaGetSymbolAddress((void**)&hs,     g_hs);
    cudaGetSymbolAddress((void**)&agg0,   g_agg0);
    cudaGetSymbolAddress((void**)&zA,     g_zA);
    cudaGetSymbolAddress((void**)&zB,     g_zB);
    cudaGetSymbolAddress((void**)&agT,    g_agT);
    cudaGetSymbolAddress((void**)&sparse, g_sparse);
    cudaGetSymbolAddress((void**)&strug,  g_strug);
    cudaGetSymbolAddress((void**)&wTh,    g_wTh);
    cudaGetSymbolAddress((void**)&deg,    g_deg);
    cudaGetSymbolAddress((void**)&rowptr, g_rowptr);
    cudaGetSymbolAddress((void**)&cursor, g_cursor);
    cudaGetSymbolAddress((void**)&colsrc, g_colsrc);
    cudaGetSymbolAddress((void**)&ng,     g_ng);
    cudaGetSymbolAddress((void**)&eg,     g_eg);
    cudaGetSymbolAddress((void**)&bsum,   g_bsum);
    cudaGetSymbolAddress((void**)&boff,   g_boff);
    cudaGetSymbolAddress((void**)&xidx,   g_xidx);
    cudaGetSymbolAddress((void**)&xcnt,   g_xcnt);

    cudaFuncSetAttribute(k_tmma, cudaFuncAttributeMaxDynamicSharedMemorySize, TM_SMEM);

    const size_t ZSZ = (size_t)MAXN * HDIM;
    int nsb = (N + 1023) / 1024;
    int agrid = (N + 7) / 8;

    // ---- capture-root fork
    cudaEventRecord(g_sp.evA, 0);

    // encode stream: h + h16
    cudaStreamWaitEvent(g_sp.s[9], g_sp.evA, 0);
    k_encode<<<N, 256, 0, g_sp.s[9]>>>(x, W_enc, b_enc, h, h16, N);
    cudaEventRecord(g_sp.evE, g_sp.s[9]);

    // router stream: pack + histograms + structural + (wait h) gemm + gates
    cudaStream_t rs = g_sp.s[8];
    cudaStreamWaitEvent(rs, g_sp.evA, 0);
    cudaMemsetAsync(ng,   0, NGRAPH * sizeof(int), rs);
    cudaMemsetAsync(eg,   0, NGRAPH * sizeof(int), rs);
    cudaMemsetAsync(xcnt, 0, NEXP * sizeof(int), rs);
    k_pack<<<24 * 256 * 512 / 256, 256, 0, rs>>>(W_self, W_nei, wTh);
    k_hist_nodes<<<128, 256, 0, rs>>>(batch, ng, N);
    k_hist_edges<<<256, 256, 0, rs>>>(batch, src, eg, E);
    k_stru<<<NGRAPH, 256, 0, rs>>>(ng, eg, Wt1, bt1, Wt2, bt2, strug);
    cudaStreamWaitEvent(rs, g_sp.evE, 0);
    {
        dim3 rgrid((N + BMR - 1) / BMR, HDIM / BNR);
        k_gemm<<<rgrid, 256, 0, rs>>>(h, Ws1, bs1, N, hs);
        k_logits<<<(N + 7) / 8, 256, 0, rs>>>(hs, Ws2, bs2, strug, batch,
                                              sparse, xidx, xcnt, N);
        cudaEventRecord(g_sp.evB, rs);
    }

    // stream 0: out zero + CSR build (depends only on edge_index)
    cudaMemsetAsync(out, 0, (size_t)out_size * sizeof(float), 0);
    cudaMemsetAsync(deg, 0, (size_t)N * sizeof(int), 0);
    k_deg<<<(E + 255) / 256, 256>>>(dst, deg, E);
    k_scan1<<<nsb, 1024>>>(deg, rowptr, bsum, N);
    k_scan2<<<1, 64>>>(bsum, boff, nsb);
    k_scan3<<<nsb, 1024>>>(deg, rowptr, boff, cursor, N);
    k_sortedges<<<(E + 255) / 256, 256>>>(src, dst, cursor, colsrc, E);
    cudaStreamWaitEvent(0, g_sp.evE, 0);
    k_agg<<<agrid, 256>>>((const uint4*)h16, (uint4*)agg0, rowptr, colsrc, N, nullptr, nullptr);

    // layer-0 pack stride dependencies: needs wTh (router stream's k_pack).
    // The layer-0 merged GEMM also needs agg0 (just computed) — chain on 0.
    cudaEventRecord(g_sp.fork, 0);

    // ---- merged layer-0 GEMM for ALL experts: one wave, shared A operand
    {
        cudaStreamWaitEvent(0, g_sp.evB, 0);   // evB implies k_pack done (same stream, earlier)
        dim3 m0grid((N + 127) / 128, 2 * NEXP);
        k_tmma<<<m0grid, 256, TM_SMEM, 0>>>(h16, agg0, wTh, b_exp, N, 1, zA, nullptr,
                                            nullptr, 0, nullptr, nullptr,
                                            1, 3 * 256 * 512, (long)ZSZ, 3 * HDIM);
        cudaEventRecord(g_sp.ev0, 0);
    }

    // ---- 8 parallel expert chains, one expert each (from layer-1 onward)
    dim3 mgrid((N + 127) / 128, 2);
    for (int e = 0; e < NEXP; e++) {
        cudaStream_t st = g_sp.s[e];
        cudaStreamWaitEvent(st, g_sp.ev0, 0);
        __half* zAi = zA + (size_t)e * ZSZ;
        __half* zBi = zB + (size_t)e * ZSZ;
        __half* agi = agT + (size_t)e * ZSZ;
        const __half* wt1 = wTh + (size_t)(e * 3 + 1) * 256 * 512;
        const __half* wt2 = wTh + (size_t)(e * 3 + 2) * 256 * 512;
        const float* b_l1 = b_exp + (size_t)(e * 3 + 1) * HDIM;
        const float* b_l2 = b_exp + (size_t)(e * 3 + 2) * HDIM;
        const int* ri = xidx + (size_t)e * MAXN;
        const int* ct = xcnt + e;

        k_agg<<<agrid, 256, 0, st>>>((const uint4*)zAi, (uint4*)agi, rowptr, colsrc, N,
                                     nullptr, nullptr);
        k_tmma<<<mgrid, 256, TM_SMEM, st>>>(zAi, agi, wt1, b_l1, N, 1, zBi, nullptr,
                                            nullptr, 0, nullptr, nullptr, 0, 0, 0, 0);
        // gates needed from here on (evB already implied by ev0 ordering, but keep explicit)
        cudaStreamWaitEvent(st, g_sp.evB, 0);
        k_agg<<<agrid, 256, 0, st>>>((const uint4*)zBi, (uint4*)agi, rowptr, colsrc, N,
                                     ri, ct);
        k_tmma<<<mgrid, 256, TM_SMEM, st>>>(zBi, agi, wt2, b_l2, N, 0, nullptr, out,
                                            sparse, e, ri, ct, 0, 0, 0, 0);
        cudaEventRecord(g_sp.join[e], st);
    }

    // ---- join back to capture stream
    for (int e = 0; e < NEXP; e++) cudaStreamWaitEvent(0, g_sp.join[e], 0);
}

// round 17
// speedup vs baseline: 1.0109x; 1.0109x over previous
#include <cuda_runtime.h>
#include <cuda_fp16.h>
#include <cstdint>
#include <cstddef>

// ---------------------------------------------------------------------------
// GraphMoEDualRouter — GB300 sm_103a.
// Round 16: merged layer-0 GEMM gated on evP (pack-done) instead of evB
// (router-done) — router path back off the dense critical path; also closes
// the round-14 latent pack race. Everything else from round 15.
// ---------------------------------------------------------------------------

#define HDIM 256
#define NEXP 8
#define NGRAPH 64
#define MAXN 50176
#define MAXE 1600000

typedef unsigned long long ull;

// ---- scratch (static device memory; allocation is forbidden) ----
__device__ float  g_h    [MAXN * HDIM];                 // fp32 h (router)
__device__ __half g_h16  [MAXN * HDIM];                 // fp16 h (experts)
__device__ float  g_hs   [MAXN * HDIM];                 // router hidden
__device__ __half g_agg0 [MAXN * HDIM];
__device__ __half g_zA   [NEXP][MAXN * HDIM];
__device__ __half g_zB   [NEXP][MAXN * HDIM];
__device__ __half g_agT  [NEXP][MAXN * HDIM];
__device__ float  g_sparse[MAXN * NEXP];
__device__ int    g_xidx  [NEXP][MAXN];                 // per-expert gated nodes
__device__ int    g_xcnt  [NEXP];
__device__ int    g_deg   [MAXN];
__device__ int    g_rowptr[MAXN + 1];
__device__ int    g_cursor[MAXN];
__device__ int    g_colsrc[MAXE];
__device__ int    g_bsum  [64];
__device__ int    g_boff  [64];
__device__ int    g_ng[NGRAPH];
__device__ int    g_eg[NGRAPH];
__device__ float  g_strug[NGRAPH * NEXP];
// packed transposed fp16 weights: [24 mats][256 nrows][512 k]
__device__ __half g_wTh[24 * 256 * 512];

// ---- host-side streams/events (created once, pre-main; host resources only)
struct StreamPool {
    cudaStream_t s[10];       // 0-7 expert chains, 8 router, 9 encode
    cudaEvent_t evA, evB, evE, evP, ev0, join[NEXP];
    StreamPool() {
        for (int i = 0; i < 10; i++)
            cudaStreamCreateWithFlags(&s[i], cudaStreamNonBlocking);
        cudaEventCreateWithFlags(&evA,  cudaEventDisableTiming);
        cudaEventCreateWithFlags(&evB,  cudaEventDisableTiming);
        cudaEventCreateWithFlags(&evE,  cudaEventDisableTiming);
        cudaEventCreateWithFlags(&evP,  cudaEventDisableTiming);
        cudaEventCreateWithFlags(&ev0,  cudaEventDisableTiming);
        for (int i = 0; i < NEXP; i++)
            cudaEventCreateWithFlags(&join[i], cudaEventDisableTiming);
    }
};
static StreamPool g_sp;

// ---- helpers ----
__device__ __forceinline__ ull pack2(float lo, float hi) {
    ull r; asm("mov.b64 %0, {%1, %2};" : "=l"(r) : "f"(lo), "f"(hi)); return r;
}
__device__ __forceinline__ void fma2acc(ull& d, ull a, ull b) {
    asm("fma.rn.f32x2 %0, %1, %2, %0;" : "+l"(d) : "l"(a), "l"(b));
}
__device__ __forceinline__ void unpack2(ull v, float& lo, float& hi) {
    asm("mov.b64 {%0, %1}, %2;" : "=f"(lo), "=f"(hi) : "l"(v));
}
__device__ __forceinline__ void mma_f16(float* d, const uint32_t* a, const uint32_t* b) {
    asm volatile(
        "mma.sync.aligned.m16n8k16.row.col.f32.f16.f16.f32 "
        "{%0,%1,%2,%3}, {%4,%5,%6,%7}, {%8,%9}, {%0,%1,%2,%3};"
        : "+f"(d[0]), "+f"(d[1]), "+f"(d[2]), "+f"(d[3])
        : "r"(a[0]), "r"(a[1]), "r"(a[2]), "r"(a[3]), "r"(b[0]), "r"(b[1]));
}
__device__ __forceinline__ void ldsm_x4(uint32_t& r0, uint32_t& r1,
                                        uint32_t& r2, uint32_t& r3, uint32_t addr) {
    asm volatile("ldmatrix.sync.aligned.m8n8.x4.shared.b16 {%0,%1,%2,%3}, [%4];"
        : "=r"(r0), "=r"(r1), "=r"(r2), "=r"(r3) : "r"(addr));
}
__device__ __forceinline__ uint32_t smem_u32(const void* p) {
    uint32_t a;
    asm("{ .reg .u64 t; cvta.to.shared.u64 t, %1; cvt.u32.u64 %0, t; }" : "=r"(a) : "l"(p));
    return a;
}
__device__ __forceinline__ void cp16(uint32_t dst, const void* src, int sz) {
    asm volatile("cp.async.cg.shared.global [%0], [%1], 16, %2;"
                 :: "r"(dst), "l"(src), "r"(sz) : "memory");
}
__device__ __forceinline__ void cp16u(uint32_t dst, const void* src) {
    asm volatile("cp.async.cg.shared.global [%0], [%1], 16;"
                 :: "r"(dst), "l"(src) : "memory");
}
__device__ __forceinline__ void acc8(float* a, uint4 v) {
    const __half2* p = (const __half2*)&v;
    #pragma unroll
    for (int q = 0; q < 4; q++) {
        float2 f = __half22float2(p[q]);
        a[2 * q]     += f.x;
        a[2 * q + 1] += f.y;
    }
}

// ===========================================================================
// Small kernels
// ===========================================================================
__global__ void k_hist_nodes(const int* __restrict__ batch, int* __restrict__ ng, int n) {
    __shared__ int sh[NGRAPH];
    if (threadIdx.x < NGRAPH) sh[threadIdx.x] = 0;
    __syncthreads();
    for (int i = blockIdx.x * blockDim.x + threadIdx.x; i < n; i += gridDim.x * blockDim.x)
        atomicAdd(&sh[batch[i]], 1);
    __syncthreads();
    if (threadIdx.x < NGRAPH) atomicAdd(&ng[threadIdx.x], sh[threadIdx.x]);
}

__global__ void k_hist_edges(const int* __restrict__ batch, const int* __restrict__ src,
                             int* __restrict__ eg, int e) {
    __shared__ int sh[NGRAPH];
    if (threadIdx.x < NGRAPH) sh[threadIdx.x] = 0;
    __syncthreads();
    for (int i = blockIdx.x * blockDim.x + threadIdx.x; i < e; i += gridDim.x * blockDim.x)
        atomicAdd(&sh[batch[src[i]]], 1);
    __syncthreads();
    if (threadIdx.x < NGRAPH) atomicAdd(&eg[threadIdx.x], sh[threadIdx.x]);
}

__global__ void k_stru(const int* __restrict__ ng, const int* __restrict__ eg,
                       const float* __restrict__ Wt1, const float* __restrict__ bt1,
                       const float* __restrict__ Wt2, const float* __restrict__ bt2,
                       float* __restrict__ strug) {
    int g = blockIdx.x;
    float fn = log1pf((float)ng[g]);
    float fe = log1pf((float)eg[g]);
    __shared__ float hid[HDIM];
    int j = threadIdx.x;
    hid[j] = fmaxf(fmaf(fn, Wt1[j], fmaf(fe, Wt1[HDIM + j], bt1[j])), 0.0f);
    __syncthreads();
    int w = threadIdx.x >> 5, lane = threadIdx.x & 31;
    if (w < NEXP) {
        float acc = 0.f;
        for (int k = lane; k < HDIM; k += 32) acc = fmaf(hid[k], Wt2[k * NEXP + w], acc);
        #pragma unroll
        for (int off = 16; off; off >>= 1) acc += __shfl_down_sync(0xffffffffu, acc, off);
        if (lane == 0) strug[g * NEXP + w] = acc + bt2[w];
    }
}

__global__ void k_encode(const float* __restrict__ x, const float* __restrict__ W,
                         const float* __restrict__ b, float* __restrict__ h,
                         __half* __restrict__ h16, int n) {
    int node = blockIdx.x;
    if (node >= n) return;
    __shared__ float xs[6];
    if (threadIdx.x < 6) xs[threadIdx.x] = x[node * 10 + 4 + threadIdx.x];
    __syncthreads();
    int j = threadIdx.x;
    float acc = b[j];
    #pragma unroll
    for (int k = 0; k < 6; k++) acc = fmaf(xs[k], W[k * HDIM + j], acc);
    float v = fmaxf(acc, 0.0f);
    h[(size_t)node * HDIM + j] = v;
    h16[(size_t)node * HDIM + j] = __float2half_rn(v);
}

// ===========================================================================
// FFMA fp32 GEMM — router hidden layer only (top-2 selection needs exactness)
// ===========================================================================
#define BMR 128
#define BNR 64
#define BKR 16

__global__ __launch_bounds__(256) void k_gemm(
    const float* __restrict__ A, const float* __restrict__ W1,
    const float* __restrict__ bias, int n, float* __restrict__ C)
{
    __shared__ __align__(16) float As[BKR][BMR + 2];
    __shared__ __align__(16) float Ws[BKR][BNR];

    int m0 = blockIdx.x * BMR;
    int n0 = blockIdx.y * BNR;
    int tid = threadIdx.x;
    int tm = tid >> 4;
    int tn = tid & 15;

    ull acc2[4][4];
    #pragma unroll
    for (int i = 0; i < 4; i++)
        #pragma unroll
        for (int j = 0; j < 4; j++) acc2[i][j] = 0ull;

    for (int kc = 0; kc < HDIM; kc += BKR) {
        #pragma unroll
        for (int u = 0; u < 2; u++) {
            int idx = tid + u * 256;
            int row = idx >> 2;
            int kq  = idx & 3;
            float4 v = make_float4(0.f, 0.f, 0.f, 0.f);
            int gr = m0 + row;
            if (gr < n) v = *(const float4*)(A + (size_t)gr * HDIM + kc + kq * 4);
            As[kq * 4 + 0][row] = v.x;
            As[kq * 4 + 1][row] = v.y;
            As[kq * 4 + 2][row] = v.z;
            As[kq * 4 + 3][row] = v.w;
        }
        {
            int kk = tid >> 4, nq = tid & 15;
            float4 w = *(const float4*)(W1 + (size_t)(kc + kk) * HDIM + n0 + nq * 4);
            *(float4*)&Ws[kk][nq * 4] = w;
        }
        __syncthreads();
        #pragma unroll
        for (int kk = 0; kk < BKR; kk++) {
            ull a2[4];
            #pragma unroll
            for (int i2 = 0; i2 < 4; i2++)
                a2[i2] = *(const ull*)&As[kk][tm * 8 + i2 * 2];
            #pragma unroll
            for (int j = 0; j < 4; j++) {
                float bb = Ws[kk][tn * 4 + j];
                ull b2 = pack2(bb, bb);
                #pragma unroll
                for (int i2 = 0; i2 < 4; i2++) fma2acc(acc2[i2][j], a2[i2], b2);
            }
        }
        __syncthreads();
    }

    float4 bb4 = *(const float4*)&bias[n0 + tn * 4];
    #pragma unroll
    for (int i2 = 0; i2 < 4; i2++) {
        float4 vlo, vhi;
        unpack2(acc2[i2][0], vlo.x, vhi.x);
        unpack2(acc2[i2][1], vlo.y, vhi.y);
        unpack2(acc2[i2][2], vlo.z, vhi.z);
        unpack2(acc2[i2][3], vlo.w, vhi.w);
        #pragma unroll
        for (int rr = 0; rr < 2; rr++) {
            int row = m0 + tm * 8 + i2 * 2 + rr;
            if (row >= n) continue;
            float4 v = rr ? vhi : vlo;
            v.x = fmaxf(v.x + bb4.x, 0.f); v.y = fmaxf(v.y + bb4.y, 0.f);
            v.z = fmaxf(v.z + bb4.z, 0.f); v.w = fmaxf(v.w + bb4.w, 0.f);
            *(float4*)(C + (size_t)row * HDIM + n0 + tn * 4) = v;
        }
    }
}

// ===========================================================================
// Router logits + top-2 sparse gates + per-expert compacted node lists
// ===========================================================================
__global__ void k_logits(const float* __restrict__ hs, const float* __restrict__ Ws2,
                         const float* __restrict__ bs2, const float* __restrict__ strug,
                         const int* __restrict__ batch, float* __restrict__ sparse,
                         int* __restrict__ xidx, int* __restrict__ xcnt, int n) {
    int warp = (blockIdx.x * blockDim.x + threadIdx.x) >> 5;
    int lane = threadIdx.x & 31;
    if (warp >= n) return;
    const float* row = hs + (size_t)warp * HDIM;
    float acc[NEXP];
    #pragma unroll
    for (int o = 0; o < NEXP; o++) acc[o] = 0.f;
    for (int k = lane; k < HDIM; k += 32) {
        float v = row[k];
        const float* w2 = Ws2 + k * NEXP;
        #pragma unroll
        for (int o = 0; o < NEXP; o++) acc[o] = fmaf(v, w2[o], acc[o]);
    }
    #pragma unroll
    for (int o = 0; o < NEXP; o++)
        #pragma unroll
        for (int off = 16; off; off >>= 1) acc[o] += __shfl_down_sync(0xffffffffu, acc[o], off);
    if (lane == 0) {
        int g = batch[warp];
        float lg[NEXP];
        #pragma unroll
        for (int o = 0; o < NEXP; o++)
            lg[o] = 0.5f * (acc[o] + bs2[o]) + 0.5f * strug[g * NEXP + o];
        float m1 = -3.4e38f; int i1 = 0;
        #pragma unroll
        for (int o = 0; o < NEXP; o++) if (lg[o] > m1) { m1 = lg[o]; i1 = o; }
        float m2 = -3.4e38f; int i2 = 0;
        #pragma unroll
        for (int o = 0; o < NEXP; o++) if (o != i1 && lg[o] > m2) { m2 = lg[o]; i2 = o; }
        float e2 = __expf(m2 - m1);
        float inv = 1.0f / (1.0f + e2);
        float* srow = sparse + (size_t)warp * NEXP;
        #pragma unroll
        for (int o = 0; o < NEXP; o++) srow[o] = 0.f;
        srow[i1] = inv;
        srow[i2] = e2 * inv;
        int p1 = atomicAdd(&xcnt[i1], 1);
        xidx[i1 * MAXN + p1] = warp;
        int p2 = atomicAdd(&xcnt[i2], 1);
        xidx[i2 * MAXN + p2] = warp;
    }
}

// ===========================================================================
// CSR build: counting sort by dst with 3-phase multi-block scan
// ===========================================================================
__global__ void k_deg(const int* __restrict__ dst, int* __restrict__ deg, int e) {
    int i = blockIdx.x * blockDim.x + threadIdx.x;
    if (i < e) atomicAdd(&deg[dst[i]], 1);
}

__global__ void k_scan1(const int* __restrict__ deg, int* __restrict__ rowptr,
                        int* __restrict__ bsum, int n) {
    __shared__ int sh[1024];
    int i = blockIdx.x * 1024 + threadIdx.x;
    int v = (i < n) ? deg[i] : 0;
    sh[threadIdx.x] = v;
    __syncthreads();
    #pragma unroll
    for (int off = 1; off < 1024; off <<= 1) {
        int t = (threadIdx.x >= (unsigned)off) ? sh[threadIdx.x - off] : 0;
        __syncthreads();
        sh[threadIdx.x] += t;
        __syncthreads();
    }
    if (i < n) rowptr[i + 1] = sh[threadIdx.x];
    if (threadIdx.x == 1023) bsum[blockIdx.x] = sh[1023];
}

__global__ void k_scan2(const int* __restrict__ bsum, int* __restrict__ boff, int nb) {
    __shared__ int sh[64];
    int i = threadIdx.x;
    int orig = (i < nb) ? bsum[i] : 0;
    sh[i] = orig;
    __syncthreads();
    #pragma unroll
    for (int off = 1; off < 64; off <<= 1) {
        int t = (i >= off) ? sh[i - off] : 0;
        __syncthreads();
        sh[i] += t;
        __syncthreads();
    }
    if (i < nb) boff[i] = sh[i] - orig;
}

__global__ void k_scan3(const int* __restrict__ deg, int* __restrict__ rowptr,
                        const int* __restrict__ boff, int* __restrict__ cursor, int n) {
    int i = blockIdx.x * 1024 + threadIdx.x;
    if (i == 0) rowptr[0] = 0;
    if (i < n) {
        int inc = rowptr[i + 1] + boff[blockIdx.x];
        rowptr[i + 1] = inc;
        cursor[i] = inc - deg[i];
    }
}

__global__ void k_sortedges(const int* __restrict__ src, const int* __restrict__ dst,
                            int* __restrict__ cursor, int* __restrict__ colsrc, int e) {
    int i = blockIdx.x * blockDim.x + threadIdx.x;
    if (i < e) {
        int d = dst[i];
        int p = atomicAdd(&cursor[d], 1);
        colsrc[p] = src[i];
    }
}

// ===========================================================================
// fp16 CSR gather aggregation (fp32 accum) — warp per node, LDG.128 lanes.
// ===========================================================================
__global__ __launch_bounds__(256) void k_agg(const uint4* __restrict__ z,
                                             uint4* __restrict__ agg,
                                             const int* __restrict__ rowptr,
                                             const int* __restrict__ colsrc, int n,
                                             const int* __restrict__ ridx,
                                             const int* __restrict__ cntp) {
    int w = blockIdx.x * 8 + (threadIdx.x >> 5);
    int lane = threadIdx.x & 31;
    int cnt = (ridx != nullptr) ? *cntp : n;
    if (w >= cnt) return;
    int node = (ridx != nullptr) ? ridx[w] : w;
    int s0 = rowptr[node], s1 = rowptr[node + 1];

    float a0[8], a1[8], a2[8], a3[8];
    #pragma unroll
    for (int k = 0; k < 8; k++) { a0[k] = a1[k] = a2[k] = a3[k] = 0.f; }

    int i = s0;
    for (; i + 3 < s1; i += 4) {
        int sA = colsrc[i], sB = colsrc[i + 1], sC = colsrc[i + 2], sD = colsrc[i + 3];
        uint4 vA = z[(size_t)sA * 32 + lane];
        uint4 vB = z[(size_t)sB * 32 + lane];
        uint4 vC = z[(size_t)sC * 32 + lane];
        uint4 vD = z[(size_t)sD * 32 + lane];
        acc8(a0, vA); acc8(a1, vB); acc8(a2, vC); acc8(a3, vD);
    }
    for (; i < s1; i++) acc8(a0, z[(size_t)colsrc[i] * 32 + lane]);

    uint4 o;
    __half2* op = (__half2*)&o;
    #pragma unroll
    for (int q = 0; q < 4; q++) {
        float rx = (a0[2 * q]     + a1[2 * q])     + (a2[2 * q]     + a3[2 * q]);
        float ry = (a0[2 * q + 1] + a1[2 * q + 1]) + (a2[2 * q + 1] + a3[2 * q + 1]);
        op[q] = __floats2half2_rn(rx, ry);
    }
    agg[(size_t)node * 32 + lane] = o;
}

// ===========================================================================
// Weight pack
// ===========================================================================
__global__ void k_pack(const float* __restrict__ Wself, const float* __restrict__ Wnei,
                       __half* __restrict__ wTh) {
    int idx = blockIdx.x * 256 + threadIdx.x;
    int k = idx & 511;
    int rem = idx >> 9;
    int nrow = rem & 255;
    int mat = rem >> 8;
    const float* srcp = (k < 256) ? Wself : Wnei;
    int kk = k & 255;
    wTh[idx] = __float2half_rn(srcp[((size_t)mat * 256 + kk) * 256 + nrow]);
}

// ===========================================================================
// fp16 mma.sync dual GEMM; ldmatrix fragment loads; optional row list.
// Expert-batched mode (ebatch != 0): blockIdx.y in [0, 2*NEXP).
// Final mode (Cf != null): out[node] += gate * val via fp32 atomicAdd.
// ===========================================================================
#define PADH 72
#define HBUF (128 * PADH)
#define TM_SMEM (4 * HBUF * 2)

__global__ __launch_bounds__(256, 2) void k_tmma(
    const __half* __restrict__ Az, const __half* __restrict__ Ag,
    const __half* __restrict__ WTh, const float* __restrict__ bias,
    int n, int relu, __half* __restrict__ Ch, float* __restrict__ Cf,
    const float* __restrict__ sparse, int expert,
    const int* __restrict__ ridx, const int* __restrict__ cntp,
    int ebatch, int wstep, long cstep, int bstep)
{
    extern __shared__ __half smh[];
    __shared__ int rid_s[128];
    uint32_t sbase = smem_u32(smh);

    int tid = threadIdx.x;
    int warp = tid >> 5, lane = tid & 31;
    int m0 = blockIdx.x * 128;
    int n0;
    if (ebatch) {
        int eb = blockIdx.y >> 1;
        n0 = (blockIdx.y & 1) * 128;
        WTh  += (size_t)eb * wstep;
        bias += (size_t)eb * bstep;
        Ch   += (size_t)eb * cstep;
    } else {
        n0 = blockIdx.y * 128;
    }
    int m_off = (warp >> 1) * 32;
    int n_off = (warp & 1) * 64;
    int g = lane >> 2, t = lane & 3;

    int mrows = (cntp != nullptr) ? *cntp : n;
    if (m0 >= mrows) return;

    if (tid < 128) {
        int gr = m0 + tid;
        rid_s[tid] = (gr < mrows) ? ((ridx != nullptr) ? ridx[gr] : gr) : 0;
    }
    __syncthreads();

    float acc[2][8][4];
    #pragma unroll
    for (int i = 0; i < 2; i++)
        #pragma unroll
        for (int j = 0; j < 8; j++)
            #pragma unroll
            for (int r = 0; r < 4; r++) acc[i][j][r] = 0.f;

    auto issue_chunk = [&](int c, int buf) {
        const __half* Asrc = (c < 4) ? Az : Ag;
        int kb = (c & 3) * 64;
        uint32_t abase = sbase + (uint32_t)buf * (HBUF * 2);
        uint32_t bbase = sbase + (uint32_t)(2 + buf) * (HBUF * 2);
        #pragma unroll
        for (int i = 0; i < 4; i++) {
            int idx = tid + i * 256;
            int row = idx >> 3, q = idx & 7;
            int gr = m0 + row;
            int node = rid_s[row];
            cp16(abase + (uint32_t)(row * (PADH * 2) + q * 16),
                 Asrc + (size_t)node * HDIM + kb + q * 8,
                 (gr < mrows) ? 16 : 0);
            cp16u(bbase + (uint32_t)(row * (PADH * 2) + q * 16),
                  WTh + (size_t)(n0 + row) * 512 + c * 64 + q * 8);
        }
        asm volatile("cp.async.commit_group;" ::: "memory");
    };

    int a_row = m_off + (lane & 7) + ((lane >> 3) & 1) * 8;
    int a_kh  = (lane >> 4) * 8;
    uint32_t a_off0 = (uint32_t)(a_row * PADH + a_kh) * 2;
    int b_row = n_off + ((lane >> 4) & 1) * 8 + (lane & 7);
    int b_kh  = ((lane >> 3) & 1) * 8;
    uint32_t b_off0 = (uint32_t)(b_row * PADH + b_kh) * 2;

    issue_chunk(0, 0);

    for (int c = 0; c < 8; c++) {
        int buf = c & 1;
        if (c < 7) {
            issue_chunk(c + 1, buf ^ 1);
            asm volatile("cp.async.wait_group 1;" ::: "memory");
        } else {
            asm volatile("cp.async.wait_group 0;" ::: "memory");
        }
        __syncthreads();

        uint32_t a_sm = sbase + (uint32_t)buf * (HBUF * 2) + a_off0;
        uint32_t b_sm = sbase + (uint32_t)(2 + buf) * (HBUF * 2) + b_off0;
        #pragma unroll
        for (int ks = 0; ks < 4; ks++) {
            uint32_t koff = (uint32_t)(ks * 16) * 2;
            uint32_t af[2][4], bf[8][2];
            ldsm_x4(af[0][0], af[0][1], af[0][2], af[0][3], a_sm + koff);
            ldsm_x4(af[1][0], af[1][1], af[1][2], af[1][3],
                    a_sm + (uint32_t)(16 * PADH) * 2 + koff);
            #pragma unroll
            for (int q = 0; q < 4; q++)
                ldsm_x4(bf[2 * q][0], bf[2 * q][1], bf[2 * q + 1][0], bf[2 * q + 1][1],
                        b_sm + (uint32_t)(q * 16 * PADH) * 2 + koff);
            #pragma unroll
            for (int i = 0; i < 2; i++)
                #pragma unroll
                for (int j = 0; j < 8; j++)
                    mma_f16(acc[i][j], af[i], bf[j]);
        }
        __syncthreads();
    }

    // ---- epilogue ----
    #pragma unroll
    for (int i = 0; i < 2; i++) {
        int l0 = m_off + i * 16 + g;
        int l1 = l0 + 8;
        bool v0r = (m0 + l0) < mrows;
        bool v1r = (m0 + l1) < mrows;
        int node0 = rid_s[l0];
        int node1 = rid_s[l1];
        float s0 = 0.f, s1 = 0.f;
        if (Cf != nullptr) {
            if (v0r) s0 = sparse[(size_t)node0 * NEXP + expert];
            if (v1r) s1 = sparse[(size_t)node1 * NEXP + expert];
        }
        #pragma unroll
        for (int j = 0; j < 8; j++) {
            int col = n0 + n_off + j * 8 + 2 * t;
            float2 bb2 = *(const float2*)(bias + col);
            float2 v0, v1;
            v0.x = acc[i][j][0] + bb2.x; v0.y = acc[i][j][1] + bb2.y;
            v1.x = acc[i][j][2] + bb2.x; v1.y = acc[i][j][3] + bb2.y;
            if (relu) {
                v0.x = fmaxf(v0.x, 0.f); v0.y = fmaxf(v0.y, 0.f);
                v1.x = fmaxf(v1.x, 0.f); v1.y = fmaxf(v1.y, 0.f);
            }
            if (Cf != nullptr) {
                if (v0r) {
                    float* op = Cf + (size_t)node0 * HDIM + col;
                    atomicAdd(op,     s0 * v0.x);
                    atomicAdd(op + 1, s0 * v0.y);
                }
                if (v1r) {
                    float* op = Cf + (size_t)node1 * HDIM + col;
                    atomicAdd(op,     s1 * v1.x);
                    atomicAdd(op + 1, s1 * v1.y);
                }
            } else {
                if (v0r) *(__half2*)(Ch + (size_t)node0 * HDIM + col) = __floats2half2_rn(v0.x, v0.y);
                if (v1r) *(__half2*)(Ch + (size_t)node1 * HDIM + col) = __floats2half2_rn(v1.x, v1.y);
            }
        }
    }
}

// ===========================================================================
// host launch
// ===========================================================================
extern "C" void kernel_launch(void* const* d_in, const int* in_sizes, int n_in,
                              void* d_out, int out_size) {
    const float* x      = (const float*)d_in[0];
    const int*   ei     = (const int*)  d_in[1];
    const int*   batch  = (const int*)  d_in[2];
    const float* W_enc  = (const float*)d_in[3];
    const float* b_enc  = (const float*)d_in[4];
    const float* Ws1    = (const float*)d_in[5];
    const float* bs1    = (const float*)d_in[6];
    const float* Ws2    = (const float*)d_in[7];
    const float* bs2    = (const float*)d_in[8];
    const float* Wt1    = (const float*)d_in[9];
    const float* bt1    = (const float*)d_in[10];
    const float* Wt2    = (const float*)d_in[11];
    const float* bt2    = (const float*)d_in[12];
    const float* W_self = (const float*)d_in[13];
    const float* W_nei  = (const float*)d_in[14];
    const float* b_exp  = (const float*)d_in[15];

    int N = in_sizes[0] / 10;
    int E = in_sizes[1] / 2;
    const int* src = ei;
    const int* dst = ei + E;
    float* out = (float*)d_out;

    float *h, *hs, *sparse, *strug;
    __half *h16, *agg0, *zA, *zB, *agT, *wTh;
    int *deg, *rowptr, *cursor, *colsrc, *ng, *eg, *bsum, *boff, *xidx, *xcnt;
    cudaGetSymbolAddress((void**)&h,      g_h);
    cudaGetSymbolAddress((void**)&h16,    g_h16);
    cudaGetSymbolAddress((void**)&hs,     g_hs);
    cudaGetSymbolAddress((void**)&agg0,   g_agg0);
    cudaGetSymbolAddress((void**)&zA,     g_zA);
    cudaGetSymbolAddress((void**)&zB,     g_zB);
    cudaGetSymbolAddress((void**)&agT,    g_agT);
    cudaGetSymbolAddress((void**)&sparse, g_sparse);
    cudaGetSymbolAddress((void**)&strug,  g_strug);
    cudaGetSymbolAddress((void**)&wTh,    g_wTh);
    cudaGetSymbolAddress((void**)&deg,    g_deg);
    cudaGetSymbolAddress((void**)&rowptr, g_rowptr);
    cudaGetSymbolAddress((void**)&cursor, g_cursor);
    cudaGetSymbolAddress((void**)&colsrc, g_colsrc);
    cudaGetSymbolAddress((void**)&ng,     g_ng);
    cudaGetSymbolAddress((void**)&eg,     g_eg);
    cudaGetSymbolAddress((void**)&bsum,   g_bsum);
    cudaGetSymbolAddress((void**)&boff,   g_boff);
    cudaGetSymbolAddress((void**)&xidx,   g_xidx);
    cudaGetSymbolAddress((void**)&xcnt,   g_xcnt);

    cudaFuncSetAttribute(k_tmma, cudaFuncAttributeMaxDynamicSharedMemorySize, TM_SMEM);

    const size_t ZSZ = (size_t)MAXN * HDIM;
    int nsb = (N + 1023) / 1024;
    int agrid = (N + 7) / 8;

    // ---- capture-root fork
    cudaEventRecord(g_sp.evA, 0);

    // encode stream: h + h16
    cudaStreamWaitEvent(g_sp.s[9], g_sp.evA, 0);
    k_encode<<<N, 256, 0, g_sp.s[9]>>>(x, W_enc, b_enc, h, h16, N);
    cudaEventRecord(g_sp.evE, g_sp.s[9]);

    // router stream: pack (-> evP) + histograms + structural + (wait h) gemm + gates
    cudaStream_t rs = g_sp.s[8];
    cudaStreamWaitEvent(rs, g_sp.evA, 0);
    cudaMemsetAsync(ng,   0, NGRAPH * sizeof(int), rs);
    cudaMemsetAsync(eg,   0, NGRAPH * sizeof(int), rs);
    cudaMemsetAsync(xcnt, 0, NEXP * sizeof(int), rs);
    k_pack<<<24 * 256 * 512 / 256, 256, 0, rs>>>(W_self, W_nei, wTh);
    cudaEventRecord(g_sp.evP, rs);                      // pack done (weights ready)
    k_hist_nodes<<<128, 256, 0, rs>>>(batch, ng, N);
    k_hist_edges<<<256, 256, 0, rs>>>(batch, src, eg, E);
    k_stru<<<NGRAPH, 256, 0, rs>>>(ng, eg, Wt1, bt1, Wt2, bt2, strug);
    cudaStreamWaitEvent(rs, g_sp.evE, 0);
    {
        dim3 rgrid((N + BMR - 1) / BMR, HDIM / BNR);
        k_gemm<<<rgrid, 256, 0, rs>>>(h, Ws1, bs1, N, hs);
        k_logits<<<(N + 7) / 8, 256, 0, rs>>>(hs, Ws2, bs2, strug, batch,
                                              sparse, xidx, xcnt, N);
        cudaEventRecord(g_sp.evB, rs);
    }

    // stream 0: out zero + CSR build (depends only on edge_index)
    cudaMemsetAsync(out, 0, (size_t)out_size * sizeof(float), 0);
    cudaMemsetAsync(deg, 0, (size_t)N * sizeof(int), 0);
    k_deg<<<(E + 255) / 256, 256>>>(dst, deg, E);
    k_scan1<<<nsb, 1024>>>(deg, rowptr, bsum, N);
    k_scan2<<<1, 64>>>(bsum, boff, nsb);
    k_scan3<<<nsb, 1024>>>(deg, rowptr, boff, cursor, N);
    k_sortedges<<<(E + 255) / 256, 256>>>(src, dst, cursor, colsrc, E);
    cudaStreamWaitEvent(0, g_sp.evE, 0);
    k_agg<<<agrid, 256>>>((const uint4*)h16, (uint4*)agg0, rowptr, colsrc, N, nullptr, nullptr);

    // ---- merged layer-0 GEMM for ALL experts: one wave, shared A operand.
    // Needs agg0 (stream-0 order) and packed weights (evP) — NOT the router GEMM.
    {
        cudaStreamWaitEvent(0, g_sp.evP, 0);
        dim3 m0grid((N + 127) / 128, 2 * NEXP);
        k_tmma<<<m0grid, 256, TM_SMEM, 0>>>(h16, agg0, wTh, b_exp, N, 1, zA, nullptr,
                                            nullptr, 0, nullptr, nullptr,
                                            1, 3 * 256 * 512, (long)ZSZ, 3 * HDIM);
        cudaEventRecord(g_sp.ev0, 0);
    }

    // ---- 8 parallel expert chains, one expert each (from layer-1 onward)
    dim3 mgrid((N + 127) / 128, 2);
    for (int e = 0; e < NEXP; e++) {
        cudaStream_t st = g_sp.s[e];
        cudaStreamWaitEvent(st, g_sp.ev0, 0);   // implies evP + agg0 + layer-0
        __half* zAi = zA + (size_t)e * ZSZ;
        __half* zBi = zB + (size_t)e * ZSZ;
        __half* agi = agT + (size_t)e * ZSZ;
        const __half* wt1 = wTh + (size_t)(e * 3 + 1) * 256 * 512;
        const __half* wt2 = wTh + (size_t)(e * 3 + 2) * 256 * 512;
        const float* b_l1 = b_exp + (size_t)(e * 3 + 1) * HDIM;
        const float* b_l2 = b_exp + (size_t)(e * 3 + 2) * HDIM;
        const int* ri = xidx + (size_t)e * MAXN;
        const int* ct = xcnt + e;

        k_agg<<<agrid, 256, 0, st>>>((const uint4*)zAi, (uint4*)agi, rowptr, colsrc, N,
                                     nullptr, nullptr);
        k_tmma<<<mgrid, 256, TM_SMEM, st>>>(zAi, agi, wt1, b_l1, N, 1, zBi, nullptr,
                                            nullptr, 0, nullptr, nullptr, 0, 0, 0, 0);
        // gates needed from here on
        cudaStreamWaitEvent(st, g_sp.evB, 0);
        k_agg<<<agrid, 256, 0, st>>>((const uint4*)zBi, (uint4*)agi, rowptr, colsrc, N,
                                     ri, ct);
        k_tmma<<<mgrid, 256, TM_SMEM, st>>>(zBi, agi, wt2, b_l2, N, 0, nullptr, out,
                                            sparse, e, ri, ct, 0, 0, 0, 0);
        cudaEventRecord(g_sp.join[e], st);
    }

    // ---- join back to capture stream
    for (int e = 0; e < NEXP; e++) cudaStreamWaitEvent(0, g_sp.join[e], 0);
}